// round 2
// baseline (speedup 1.0000x reference)
#include <cuda_runtime.h>

#define BB   16384
#define FF   30
#define BINS 30
#define EMB  100
#define NROW (BB*FF)        // 491520
#define NK   15             // BINS/2 packed o-pairs

// exp2 coefficients per sign branch: [0] = x>0, [1] = x<0
__device__ float g_d[2][32];

// ---------------------------------------------------------------------------
// Precompute kernel: collapse W1/Wl into two 30-vectors of exp2 coefficients.
// ---------------------------------------------------------------------------
__global__ void precompute_kernel(const float* __restrict__ W1,
                                  const float* __restrict__ Wl) {
    __shared__ float vs[2][32];
    __shared__ float us[2][32];
    int t = threadIdx.x;       // 64 threads
    int s = t >> 5;            // 0: x>0 branch, 1: x<0 branch
    int o = t & 31;

    float v = 0.f;
    if (o < BINS) {
        float w = W1[o];
        bool act = (s == 0) ? (w > 0.f) : (w < 0.f);
        v = act ? w : 0.01f * w;
    }
    vs[s][o] = v;
    __syncthreads();

    float u = 0.f;
    if (o < BINS) {
        #pragma unroll
        for (int i = 0; i < BINS; i++) u += Wl[o * BINS + i] * vs[s][i];
        u += 0.1f * v;
    }
    us[s][o] = u;
    __syncthreads();

    float dval = 0.f;
    if (o < BINS) {
        float ext = us[s][0];
        #pragma unroll
        for (int i = 1; i < BINS; i++) {
            float z = us[s][i];
            ext = (s == 0) ? fmaxf(ext, z) : fminf(ext, z);
        }
        const float T_LOG2E = 0.5f * 1.44269504088896340736f;  // T * log2(e)
        dval = T_LOG2E * (u - ext);
    }
    g_d[s][o] = dval;
}

// ---------------------------------------------------------------------------
// Main kernel. One thread per (b,f) row.
//   p_o = exp2(x*d[o]);  out_e = (sum_o p_o * W2[e][o]) / Z
// FFMA2 packs (even-o, odd-o) partial sums in one f32x2 accumulator.
// Output staged through shared for coalesced stores.
// ---------------------------------------------------------------------------

#define STG_STRIDE 36   // floats per row in staging (9 x 16B; 9 coprime 8 -> conflict-free)

__device__ __forceinline__ void ffma2(unsigned long long& acc,
                                      unsigned long long a,
                                      unsigned long long b) {
    asm("fma.rn.f32x2 %0, %1, %2, %0;" : "+l"(acc) : "l"(a), "l"(b));
}

template<int CE>
__device__ __forceinline__ void do_chunk(int e0,
                                         const float2* __restrict__ wp,
                                         const unsigned long long* p2,
                                         float invZ,
                                         float* stage,
                                         float* __restrict__ out_base,   // out + row0*EMB
                                         int tid) {
    float* stg = stage + tid * STG_STRIDE;

    #pragma unroll
    for (int eg = 0; eg < CE; eg += 4) {
        const int e = e0 + eg;
        unsigned long long a0 = 0ull, a1 = 0ull, a2 = 0ull, a3 = 0ull;
        #pragma unroll
        for (int k = 0; k < NK; k++) {
            // wp[k][e..e+3] : 4 float2 = 32B, two 16B loads (broadcast, uniform addr)
            ulonglong2 wA = *reinterpret_cast<const ulonglong2*>(wp + k * EMB + e);
            ulonglong2 wB = *reinterpret_cast<const ulonglong2*>(wp + k * EMB + e + 2);
            ffma2(a0, p2[k], wA.x);
            ffma2(a1, p2[k], wA.y);
            ffma2(a2, p2[k], wB.x);
            ffma2(a3, p2[k], wB.y);
        }
        float l0, h0, l1, h1, l2, h2, l3, h3;
        asm("mov.b64 {%0,%1}, %2;" : "=f"(l0), "=f"(h0) : "l"(a0));
        asm("mov.b64 {%0,%1}, %2;" : "=f"(l1), "=f"(h1) : "l"(a1));
        asm("mov.b64 {%0,%1}, %2;" : "=f"(l2), "=f"(h2) : "l"(a2));
        asm("mov.b64 {%0,%1}, %2;" : "=f"(l3), "=f"(h3) : "l"(a3));
        float4 r;
        r.x = (l0 + h0) * invZ;
        r.y = (l1 + h1) * invZ;
        r.z = (l2 + h2) * invZ;
        r.w = (l3 + h3) * invZ;
        *reinterpret_cast<float4*>(stg + eg) = r;   // conflict-free STS.128
    }
    __syncthreads();

    // cooperative coalesced store of this chunk (256 rows x CE cols)
    constexpr int NG = CE / 4;   // float4 per row
    #pragma unroll
    for (int it = 0; it < NG; it++) {
        int q = tid + it * 256;
        int r = q / NG, c = q % NG;
        float4 v = *reinterpret_cast<const float4*>(stage + r * STG_STRIDE + c * 4);
        *reinterpret_cast<float4*>(out_base + (size_t)r * EMB + e0 + c * 4) = v;
    }
    __syncthreads();
}

__global__ void __launch_bounds__(256, 4)
main_kernel(const float* __restrict__ x,
            const float* __restrict__ W2,
            float* __restrict__ out) {
    __shared__ float2 wp[NK * EMB];            // 12000 B: wp[k][e] = {W2[e][2k], W2[e][2k+1]}
    __shared__ float  stage[256 * STG_STRIDE]; // 36864 B
    __shared__ float  dsh[2][32];              // 256 B

    const int tid = threadIdx.x;

    for (int i = tid; i < NK * EMB; i += 256) {
        int k = i / EMB, e = i % EMB;
        float2 v;
        v.x = W2[e * BINS + 2 * k];
        v.y = W2[e * BINS + 2 * k + 1];
        wp[k * EMB + e] = v;
    }
    if (tid < 64) dsh[tid >> 5][tid & 31] = g_d[tid >> 5][tid & 31];
    __syncthreads();

    const int row = blockIdx.x * 256 + tid;
    const float xv = x[row];
    const float* d = (xv > 0.f) ? dsh[0] : dsh[1];

    unsigned long long p2[NK];
    float Z = 0.f;
    #pragma unroll
    for (int k = 0; k < NK; k++) {
        float a0 = xv * d[2 * k];
        float a1 = xv * d[2 * k + 1];
        float e0, e1;
        asm("ex2.approx.ftz.f32 %0, %1;" : "=f"(e0) : "f"(a0));
        asm("ex2.approx.ftz.f32 %0, %1;" : "=f"(e1) : "f"(a1));
        Z += e0 + e1;
        asm("mov.b64 %0, {%1, %2};" : "=l"(p2[k]) : "f"(e0), "f"(e1));
    }
    const float invZ = 1.0f / Z;

    float* out_base = out + (size_t)blockIdx.x * 256 * EMB;

    do_chunk<36>(0,  wp, p2, invZ, stage, out_base, tid);
    do_chunk<36>(36, wp, p2, invZ, stage, out_base, tid);
    do_chunk<28>(72, wp, p2, invZ, stage, out_base, tid);
}

// ---------------------------------------------------------------------------
extern "C" void kernel_launch(void* const* d_in, const int* in_sizes, int n_in,
                              void* d_out, int out_size) {
    const float* x  = (const float*)d_in[0];   // (16384, 1, 30)
    const float* W1 = (const float*)d_in[1];   // (30, 1)
    const float* Wl = (const float*)d_in[2];   // (30, 30)
    const float* W2 = (const float*)d_in[3];   // (100, 30)
    float* out = (float*)d_out;                // (16384, 3000)

    precompute_kernel<<<1, 64>>>(W1, Wl);
    main_kernel<<<NROW / 256, 256>>>(x, W2, out);
}

// round 5
// speedup vs baseline: 1.8868x; 1.8868x over previous
#include <cuda_runtime.h>
#include <cstdint>

#define BB    16384
#define FF    30
#define BINS  30
#define EMB   100
#define NROW  (BB*FF)          // 491520
#define TM    128              // rows per CTA
#define NCTAS (NROW/TM)        // 3840

#define KDIM  96               // 6 k16 steps (hi|hi|lo segments of 32)
#define NPAD  104              // 13 n8 tiles
#define AST   104              // A row stride in bf16 (208 B = 13 x 16B, conflict-free)
#define BST   104              // B row stride in bf16
#define SST   108              // stage row stride in floats (432 B, 16B-aligned rows)

#define A_BYTES (TM * AST * 2)      // 26624
#define B_BYTES (NPAD * BST * 2)    // 21632
#define STAGE_BYTES (TM * SST * 4)  // 55296
// stage overlaps A+B (both dead after the MMA loop)
#define DYN_SMEM (STAGE_BYTES + 32)

// ---------------- helpers ----------------
__device__ __forceinline__ uint32_t smem_u32(const void* p) {
    uint32_t a;
    asm("{ .reg .u64 t; cvta.to.shared.u64 t, %1; cvt.u32.u64 %0, t; }" : "=r"(a) : "l"(p));
    return a;
}
__device__ __forceinline__ void sts128(uint32_t a, uint4 v) {
    asm volatile("st.shared.v4.b32 [%0], {%1,%2,%3,%4};" :: "r"(a), "r"(v.x), "r"(v.y), "r"(v.z), "r"(v.w) : "memory");
}
__device__ __forceinline__ void sts64f(uint32_t a, float x, float y) {
    asm volatile("st.shared.v2.f32 [%0], {%1,%2};" :: "r"(a), "f"(x), "f"(y) : "memory");
}
__device__ __forceinline__ float4 lds128f(uint32_t a) {
    float4 v;
    asm volatile("ld.shared.v4.f32 {%0,%1,%2,%3}, [%4];"
                 : "=f"(v.x), "=f"(v.y), "=f"(v.z), "=f"(v.w) : "r"(a));
    return v;
}
__device__ __forceinline__ void ldm_x4(uint32_t& r0, uint32_t& r1, uint32_t& r2, uint32_t& r3, uint32_t a) {
    asm volatile("ldmatrix.sync.aligned.m8n8.x4.shared.b16 {%0,%1,%2,%3}, [%4];"
                 : "=r"(r0), "=r"(r1), "=r"(r2), "=r"(r3) : "r"(a));
}
__device__ __forceinline__ void ldm_x2(uint32_t& r0, uint32_t& r1, uint32_t a) {
    asm volatile("ldmatrix.sync.aligned.m8n8.x2.shared.b16 {%0,%1}, [%2];"
                 : "=r"(r0), "=r"(r1) : "r"(a));
}
__device__ __forceinline__ void mma_bf16(float& d0, float& d1, float& d2, float& d3,
                                         uint32_t a0, uint32_t a1, uint32_t a2, uint32_t a3,
                                         uint32_t b0, uint32_t b1) {
    asm volatile("mma.sync.aligned.m16n8k16.row.col.f32.bf16.bf16.f32 "
                 "{%0,%1,%2,%3}, {%4,%5,%6,%7}, {%8,%9}, {%0,%1,%2,%3};"
                 : "+f"(d0), "+f"(d1), "+f"(d2), "+f"(d3)
                 : "r"(a0), "r"(a1), "r"(a2), "r"(a3), "r"(b0), "r"(b1));
}
// pack: low half = bf16(lo), high half = bf16(hi)
__device__ __forceinline__ uint32_t pack_bf16x2(float lo, float hi) {
    uint32_t r;
    asm("cvt.rn.bf16x2.f32 %0, %2, %1;" : "=r"(r) : "f"(lo), "f"(hi));
    return r;
}

// ---------------- device globals ----------------
__device__ float g_d[2][32];                                 // exp2 coefficients per sign
__device__ __align__(16) unsigned short g_B2[NPAD * BST];    // Bt image: [n][k] bf16

// ---------------------------------------------------------------------------
// Precompute: g_d from W1/Wl; g_B2 = W2 hi/lo split, K-segs [w_hi|w_lo|w_hi].
// ---------------------------------------------------------------------------
__global__ void precompute_kernel(const float* __restrict__ W1,
                                  const float* __restrict__ Wl,
                                  const float* __restrict__ W2) {
    __shared__ float vs[2][32];
    __shared__ float us[2][32];
    int t = threadIdx.x;       // 128 threads

    if (t < 64) {
        int s = t >> 5, o = t & 31;
        float v = 0.f;
        if (o < BINS) {
            float w = W1[o];
            bool act = (s == 0) ? (w > 0.f) : (w < 0.f);
            v = act ? w : 0.01f * w;
        }
        vs[s][o] = v;
    }
    __syncthreads();
    if (t < 64) {
        int s = t >> 5, o = t & 31;
        float u = 0.f;
        if (o < BINS) {
            #pragma unroll
            for (int i = 0; i < BINS; i++) u += Wl[o * BINS + i] * vs[s][i];
            u += 0.1f * vs[s][o];
        }
        us[s][o] = u;
    }
    __syncthreads();
    if (t < 64) {
        int s = t >> 5, o = t & 31;
        float dval = 0.f;
        if (o < BINS) {
            float u = us[s][o];
            float ext = us[s][0];
            #pragma unroll
            for (int i = 1; i < BINS; i++) {
                float z = us[s][i];
                ext = (s == 0) ? fmaxf(ext, z) : fminf(ext, z);
            }
            const float T_LOG2E = 0.5f * 1.44269504088896340736f;
            dval = T_LOG2E * (u - ext);
        }
        g_d[s][o] = dval;
    }

    // B image: one thread per n-row
    if (t < NPAD) {
        int n = t;
        unsigned short hb[BINS], lb[BINS];
        if (n < EMB) {
            #pragma unroll
            for (int o = 0; o < BINS; o++) {
                float w = W2[n * BINS + o];
                uint32_t hp = pack_bf16x2(w, 0.f);
                unsigned short h = (unsigned short)(hp & 0xFFFF);
                float hf = __uint_as_float(((uint32_t)h) << 16);
                uint32_t lp = pack_bf16x2(w - hf, 0.f);
                hb[o] = h;
                lb[o] = (unsigned short)(lp & 0xFFFF);
            }
        } else {
            #pragma unroll
            for (int o = 0; o < BINS; o++) { hb[o] = 0; lb[o] = 0; }
        }
        for (int c = 0; c < BST; c++) {
            unsigned short bits = 0;
            if (c < 30)                 bits = hb[c];
            else if (c >= 32 && c < 62) bits = lb[c - 32];
            else if (c >= 64 && c < 94) bits = hb[c - 64];
            g_B2[n * BST + c] = bits;
        }
    }
}

// ---------------------------------------------------------------------------
// Main kernel: 128 rows/CTA, 4 warps, mma.sync m16n8k16 bf16.
// ---------------------------------------------------------------------------
__global__ void __launch_bounds__(128)
main_kernel(const float* __restrict__ x,
            float* __restrict__ out) {
    extern __shared__ char raw[];
    __shared__ float dsh[2][32];

    const int tid = threadIdx.x;
    const int wid = tid >> 5;
    const int lane = tid & 31;

    uint32_t base  = smem_u32(raw);         // 16B aligned
    uint32_t abase = base;                  // A tile  [128][104] bf16
    uint32_t bbase = base + A_BYTES;        // B tile  [104][104] bf16
    uint32_t sbase = base;                  // stage   [128][108] f32 (overlaps A+B)

    // load dsh + copy B image to smem
    if (tid < 64) dsh[tid >> 5][tid & 31] = g_d[tid >> 5][tid & 31];
    {
        const uint4* gb = reinterpret_cast<const uint4*>(g_B2);
        for (int i = tid; i < B_BYTES / 16; i += 128) sts128(bbase + i * 16u, gb[i]);
    }
    __syncthreads();

    // ---- per-row softmax probabilities (invZ folded), hi/lo split, build A row ----
    const int row = blockIdx.x * TM + tid;
    const float xv = x[row];
    const float* d = (xv > 0.f) ? dsh[0] : dsh[1];

    float p[BINS];
    float Z = 0.f;
    #pragma unroll
    for (int o = 0; o < BINS; o++) {
        float a = xv * d[o];
        float e;
        asm("ex2.approx.ftz.f32 %0, %1;" : "=f"(e) : "f"(a));
        p[o] = e;
        Z += e;
    }
    const float invZ = 1.0f / Z;

    uint32_t arow[52];
    #pragma unroll
    for (int i = 0; i < 52; i++) arow[i] = 0u;
    #pragma unroll
    for (int k = 0; k < 15; k++) {
        float p0 = p[2 * k] * invZ;
        float p1 = p[2 * k + 1] * invZ;
        uint32_t hp = pack_bf16x2(p0, p1);
        float h0 = __uint_as_float(hp << 16);
        float h1 = __uint_as_float(hp & 0xFFFF0000u);
        uint32_t lp = pack_bf16x2(p0 - h0, p1 - h1);
        arow[k]      = hp;     // cols  0..29 : p_hi
        arow[16 + k] = hp;     // cols 32..61 : p_hi
        arow[32 + k] = lp;     // cols 64..93 : p_lo
    }
    {
        uint32_t ra = abase + (uint32_t)tid * (AST * 2);
        #pragma unroll
        for (int i = 0; i < 13; i++) {
            uint4 v = make_uint4(arow[4 * i], arow[4 * i + 1], arow[4 * i + 2], arow[4 * i + 3]);
            sts128(ra + i * 16u, v);
        }
    }
    __syncthreads();

    // ---- MMA mainloop: per warp M=32 (2 m16), N=104 (13 n8), K=96 (6 k16) ----
    float acc[2][13][4];
    #pragma unroll
    for (int mi = 0; mi < 2; mi++)
        #pragma unroll
        for (int nj = 0; nj < 13; nj++)
            #pragma unroll
            for (int q = 0; q < 4; q++) acc[mi][nj][q] = 0.f;

    // ldmatrix lane address components
    const int arow_in_tile = lane & 15;          // rows 0..15
    const int achunk = lane >> 4;                // 0/1 -> +16B
    const int brow = lane & 7;                   // n-row 0..7 (x2: lanes 0..15 used)
    const int bchunk = (lane >> 3) & 1;          // 0/1 -> +16B

    #pragma unroll
    for (int kk = 0; kk < 6; kk++) {
        uint32_t a0[4], a1[4];
        {
            uint32_t aa = abase + (uint32_t)((32 * wid + arow_in_tile) * (AST * 2) + kk * 32 + achunk * 16);
            ldm_x4(a0[0], a0[1], a0[2], a0[3], aa);
            uint32_t ab = aa + 16u * (AST * 2);
            ldm_x4(a1[0], a1[1], a1[2], a1[3], ab);
        }
        #pragma unroll
        for (int nj = 0; nj < 13; nj++) {
            uint32_t b0, b1;
            uint32_t ba = bbase + (uint32_t)((8 * nj + brow) * (BST * 2) + kk * 32 + bchunk * 16);
            ldm_x2(b0, b1, ba);
            mma_bf16(acc[0][nj][0], acc[0][nj][1], acc[0][nj][2], acc[0][nj][3],
                     a0[0], a0[1], a0[2], a0[3], b0, b1);
            mma_bf16(acc[1][nj][0], acc[1][nj][1], acc[1][nj][2], acc[1][nj][3],
                     a1[0], a1[1], a1[2], a1[3], b0, b1);
        }
    }
    __syncthreads();   // all warps done reading A/B; stage may overwrite

    // ---- stage fragments to smem (f32, [128][SST]) ----
    {
        const int rr = lane >> 2;            // 0..7
        const int cc = 2 * (lane & 3);       // 0,2,4,6
        #pragma unroll
        for (int mi = 0; mi < 2; mi++) {
            const int r0 = 32 * wid + 16 * mi + rr;
            #pragma unroll
            for (int nj = 0; nj < 13; nj++) {
                const int c0 = 8 * nj + cc;
                uint32_t sa = sbase + (uint32_t)((r0 * SST + c0) * 4);
                sts64f(sa, acc[mi][nj][0], acc[mi][nj][1]);
                sts64f(sa + 8u * SST * 4u, acc[mi][nj][2], acc[mi][nj][3]);
            }
        }
    }
    __syncthreads();

    // ---- cooperative coalesced store: 128 rows x 100 cols = 3200 float4 ----
    float* outb = out + (size_t)blockIdx.x * TM * EMB;
    #pragma unroll
    for (int it = 0; it < 25; it++) {
        int q = tid + it * 128;
        int rr = q / 25, c = q % 25;
        float4 v = lds128f(sbase + (uint32_t)((rr * SST + 4 * c) * 4));
        *reinterpret_cast<float4*>(outb + (size_t)rr * EMB + 4 * c) = v;
    }
}

// ---------------------------------------------------------------------------
extern "C" void kernel_launch(void* const* d_in, const int* in_sizes, int n_in,
                              void* d_out, int out_size) {
    const float* x  = (const float*)d_in[0];   // (16384, 1, 30)
    const float* W1 = (const float*)d_in[1];   // (30, 1)
    const float* Wl = (const float*)d_in[2];   // (30, 30)
    const float* W2 = (const float*)d_in[3];   // (100, 30)
    float* out = (float*)d_out;                // (16384, 3000)

    cudaFuncSetAttribute(main_kernel, cudaFuncAttributeMaxDynamicSharedMemorySize, DYN_SMEM);

    precompute_kernel<<<1, 128>>>(W1, Wl, W2);
    main_kernel<<<NCTAS, 128, DYN_SMEM>>>(x, out);
}